// round 10
// baseline (speedup 1.0000x reference)
#include <cuda_runtime.h>
#include <cuda_fp16.h>
#include <cstdint>

#define BB 4
#define LL 4096
#define DD 128
#define HTILE 32            // KV tiles per CTA (KV-split by 2)
#define KSTR 272            // K/V smem row stride bytes (128 halfs + 16B pad)
#define KBUF (64 * KSTR)    // 17408
#define VOFFS (3 * KBUF)
#define SMEMSZ (6 * KBUF)   // 104448

// projected q (pre-scaled by log2e/sqrt(D)), k, v in fp16
__device__ __half g_qkv[3][(size_t)BB * LL * DD];
// KV-split partials
__device__ float g_po[2][(size_t)BB * LL * DD];
__device__ float g_pl[2][(size_t)BB * LL];
// pre-converted fp16 weights (scale folded) + pre-scaled fp32 bias
__device__ __half g_wh[3][DD * DD];
__device__ float  g_bs[3][DD];

// ---------------------------------------------------------------------------
// helpers
// ---------------------------------------------------------------------------
__device__ __forceinline__ uint32_t smem_u32(const void* p) {
    uint32_t a;
    asm("{ .reg .u64 t; cvta.to.shared.u64 t, %1; cvt.u32.u64 %0, t; }" : "=r"(a) : "l"(p));
    return a;
}
__device__ __forceinline__ void cp_async16(uint32_t dst, const void* src) {
    asm volatile("cp.async.cg.shared.global [%0], [%1], 16;" :: "r"(dst), "l"(src));
}
#define CP_COMMIT() asm volatile("cp.async.commit_group;" ::: "memory")
#define CP_WAIT(n)  asm volatile("cp.async.wait_group %0;" :: "n"(n) : "memory")

__device__ __forceinline__ void ldsm4(uint32_t* r, uint32_t a) {
    asm volatile("ldmatrix.sync.aligned.m8n8.x4.shared.b16 {%0,%1,%2,%3}, [%4];"
                 : "=r"(r[0]), "=r"(r[1]), "=r"(r[2]), "=r"(r[3]) : "r"(a));
}
__device__ __forceinline__ void ldsm4t(uint32_t* r, uint32_t a) {
    asm volatile("ldmatrix.sync.aligned.m8n8.x4.trans.shared.b16 {%0,%1,%2,%3}, [%4];"
                 : "=r"(r[0]), "=r"(r[1]), "=r"(r[2]), "=r"(r[3]) : "r"(a));
}
__device__ __forceinline__ void mma16816(float* c, const uint32_t* a, uint32_t b0, uint32_t b1) {
    asm volatile("mma.sync.aligned.m16n8k16.row.col.f32.f16.f16.f32 "
                 "{%0,%1,%2,%3}, {%4,%5,%6,%7}, {%8,%9}, {%0,%1,%2,%3};"
                 : "+f"(c[0]), "+f"(c[1]), "+f"(c[2]), "+f"(c[3])
                 : "r"(a[0]), "r"(a[1]), "r"(a[2]), "r"(a[3]), "r"(b0), "r"(b1));
}
__device__ __forceinline__ uint32_t ex2_h2(uint32_t x) {
    uint32_t y;
    asm("ex2.approx.f16x2 %0, %1;" : "=r"(y) : "r"(x));
    return y;
}
__device__ __forceinline__ uint32_t pack_h2(float a, float b) {
    __half2 h = __floats2half2_rn(a, b);
    return *(uint32_t*)&h;
}

// ---------------------------------------------------------------------------
// W/bias pre-convert: fp16 W with softmax scale folded; fp32 bias pre-scaled.
// ---------------------------------------------------------------------------
__global__ __launch_bounds__(256) void wconv_kernel(
    const float* __restrict__ Wq, const float* __restrict__ bq,
    const float* __restrict__ Wk, const float* __restrict__ bk,
    const float* __restrict__ Wv, const float* __restrict__ bv)
{
    const int sel = blockIdx.x >> 3;
    const int blk = blockIdx.x & 7;
    const float* W = (sel == 0) ? Wq : (sel == 1) ? Wk : Wv;
    const float* bias = (sel == 0) ? bq : (sel == 1) ? bk : bv;
    const float s = (sel == 0) ? 0.12752615f : 1.0f;   // log2(e)/sqrt(128)

    const float4* wg = (const float4*)W;
    uint2* wo = (uint2*)g_wh[sel];
    #pragma unroll
    for (int i = 0; i < 2; i++) {
        int idx = blk * 512 + threadIdx.x + i * 256;
        float4 v = wg[idx];
        wo[idx] = make_uint2(pack_h2(v.x * s, v.y * s), pack_h2(v.z * s, v.w * s));
    }
    if (blk == 0 && threadIdx.x < DD) g_bs[sel][threadIdx.x] = bias[threadIdx.x] * s;
}

// ---------------------------------------------------------------------------
// Projection v2: A-frags straight from gmem (fp32->fp16 pack in regs),
// W fp16 via cp.async, B-frags via ldmatrix. 128 rows / CTA, 8 warps x m16.
// ---------------------------------------------------------------------------
#define PJ_WB (128 * KSTR)          // 34816
#define PJ2_SMEM (PJ_WB + 512)

__global__ __launch_bounds__(256) void proj_mma(
    const float* __restrict__ x1, const float* __restrict__ x2, const float* __restrict__ x3)
{
    extern __shared__ char psm[];
    const uint32_t sb = smem_u32(psm);
    const int tid = threadIdx.x;
    const int w = tid >> 5;
    const int l = tid & 31;
    const int sel = blockIdx.x >> 7;
    const int blk = blockIdx.x & 127;

    const float* x = (sel == 0) ? x1 : (sel == 1) ? x2 : x3;

    // stage W fp16 (32KB) + bias (512B) via cp.async
    const char* wsrc = (const char*)g_wh[sel];
    #pragma unroll
    for (int i = 0; i < 8; i++) {
        int idx = tid + i * 256;
        int r = idx >> 4, c = idx & 15;
        cp_async16(sb + r * KSTR + c * 16, wsrc + idx * 16);
    }
    if (tid < 32) cp_async16(sb + PJ_WB + tid * 16, (const char*)g_bs[sel] + tid * 16);
    CP_COMMIT();

    // A fragments direct from gmem (fp32 -> fp16)
    const int row0 = blk * 128 + w * 16 + (l >> 2);
    const float* xr = x + (size_t)row0 * DD + 2 * (l & 3);
    uint32_t af[8][4];
    #pragma unroll
    for (int s = 0; s < 8; s++) {
        float2 a0 = *(const float2*)(xr + 16 * s);
        float2 a1 = *(const float2*)(xr + 8 * DD + 16 * s);
        float2 a2 = *(const float2*)(xr + 16 * s + 8);
        float2 a3 = *(const float2*)(xr + 8 * DD + 16 * s + 8);
        af[s][0] = pack_h2(a0.x, a0.y);
        af[s][1] = pack_h2(a1.x, a1.y);
        af[s][2] = pack_h2(a2.x, a2.y);
        af[s][3] = pack_h2(a3.x, a3.y);
    }

    float cY[16][4];
    #pragma unroll
    for (int j = 0; j < 16; j++)
        #pragma unroll
        for (int i = 0; i < 4; i++) cY[j][i] = 0.f;

    CP_WAIT(0);
    __syncthreads();

    #pragma unroll
    for (int j = 0; j < 16; j++) {
        const uint32_t bbase = sb + (j * 8 + (l & 7)) * KSTR + ((l >> 3) * 8) * 2;
        #pragma unroll
        for (int s2 = 0; s2 < 4; s2++) {
            uint32_t br[4];
            ldsm4(br, bbase + s2 * 64);
            mma16816(cY[j], af[2 * s2],     br[0], br[1]);
            mma16816(cY[j], af[2 * s2 + 1], br[2], br[3]);
        }
    }

    const float* bs = (const float*)(psm + PJ_WB);
    __half* o0 = g_qkv[sel] + (size_t)(blk * 128 + w * 16 + (l >> 2)) * DD;
    #pragma unroll
    for (int j = 0; j < 16; j++) {
        int c = j * 8 + 2 * (l & 3);
        float b0 = bs[c], b1 = bs[c + 1];
        *(uint32_t*)(o0 + c)          = pack_h2(cY[j][0] + b0, cY[j][1] + b1);
        *(uint32_t*)(o0 + 8 * DD + c) = pack_h2(cY[j][2] + b0, cY[j][3] + b1);
    }
}

// ---------------------------------------------------------------------------
// fp16 mma.sync flash attention, 32 q-rows/warp, chunked streaming softmax,
// register P, KV-split x2, distance-1 ldsm pipelining in S and PV loops.
// ---------------------------------------------------------------------------
__device__ __forceinline__ void load_kv(const __half* kg, const __half* vg, int t,
                                        uint32_t sb, int buf, int tid)
{
    const __half* ks = kg + (size_t)t * 64 * DD;
    const __half* vs = vg + (size_t)t * 64 * DD;
    const uint32_t kd = sb + buf * KBUF;
    const uint32_t vd = sb + VOFFS + buf * KBUF;
    #pragma unroll
    for (int i = 0; i < 8; i++) {
        int idx = tid + i * 128;
        int r = idx >> 4, c = idx & 15;
        cp_async16(kd + r * KSTR + c * 16, ks + r * DD + c * 8);
    }
    #pragma unroll
    for (int i = 0; i < 8; i++) {
        int idx = tid + i * 128;
        int r = idx >> 4, c = idx & 15;
        cp_async16(vd + r * KSTR + c * 16, vs + r * DD + c * 8);
    }
}

__global__ __launch_bounds__(128, 2) void attn_kernel()
{
    extern __shared__ char smem[];
    const uint32_t sb = smem_u32(smem);
    const int tid = threadIdx.x;
    const int w = tid >> 5;
    const int l = tid & 31;
    const int b  = blockIdx.x >> 6;
    const int qt = (blockIdx.x >> 1) & 31;
    const int h  = blockIdx.x & 1;

    const __half* qg = g_qkv[0] + ((size_t)b * LL + qt * 128) * DD;
    const __half* kg = g_qkv[1] + ((size_t)b * LL + h * 2048) * DD;
    const __half* vg = g_qkv[2] + ((size_t)b * LL + h * 2048) * DD;

    uint32_t qf[2][8][4];
    #pragma unroll
    for (int b_ = 0; b_ < 2; b_++) {
        const __half* q0 = qg + (w * 32 + b_ * 16 + (l >> 2)) * DD + 2 * (l & 3);
        #pragma unroll
        for (int s = 0; s < 8; s++) {
            qf[b_][s][0] = *(const uint32_t*)(q0 + 16 * s);
            qf[b_][s][1] = *(const uint32_t*)(q0 + 8 * DD + 16 * s);
            qf[b_][s][2] = *(const uint32_t*)(q0 + 16 * s + 8);
            qf[b_][s][3] = *(const uint32_t*)(q0 + 8 * DD + 16 * s + 8);
        }
    }

    load_kv(kg, vg, 0, sb, 0, tid); CP_COMMIT();
    load_kv(kg, vg, 1, sb, 1, tid); CP_COMMIT();

    float cO[2][16][4];
    #pragma unroll
    for (int b_ = 0; b_ < 2; b_++)
        #pragma unroll
        for (int j = 0; j < 16; j++)
            #pragma unroll
            for (int i = 0; i < 4; i++) cO[b_][j][i] = 0.f;
    float lacc[2][2] = {{0.f, 0.f}, {0.f, 0.f}};

    for (int t = 0; t < HTILE; t++) {
        if (t + 2 < HTILE) { CP_WAIT(1); } else { CP_WAIT(0); }
        __syncthreads();
        if (t + 2 < HTILE) { load_kv(kg, vg, t + 2, sb, (t + 2) % 3, tid); CP_COMMIT(); }

        const uint32_t kb = sb + (t % 3) * KBUF;
        const uint32_t vb = sb + VOFFS + (t % 3) * KBUF;

        #pragma unroll
        for (int s = 0; s < 4; s++) {        // 16-kv chunk
            float cS[2][2][4];
            #pragma unroll
            for (int b_ = 0; b_ < 2; b_++)
                #pragma unroll
                for (int jj = 0; jj < 2; jj++)
                    #pragma unroll
                    for (int i = 0; i < 4; i++) cS[b_][jj][i] = 0.f;

            // ---- S chunk: pipelined over 8 (jj,s2) ldsm steps ----
            {
                const uint32_t kr0 = kb + ((2 * s + 0) * 8 + (l & 7)) * KSTR + ((l >> 3) * 8) * 2;
                const uint32_t kr1 = kb + ((2 * s + 1) * 8 + (l & 7)) * KSTR + ((l >> 3) * 8) * 2;
                uint32_t br[2][4];
                ldsm4(br[0], kr0);
                #pragma unroll
                for (int i = 0; i < 8; i++) {
                    if (i < 7) {
                        int n = i + 1;
                        ldsm4(br[n & 1], ((n >> 2) ? kr1 : kr0) + (n & 3) * 64);
                    }
                    const int jj = i >> 2, s2 = i & 3;
                    const uint32_t* bc = br[i & 1];
                    mma16816(cS[0][jj], qf[0][2 * s2],     bc[0], bc[1]);
                    mma16816(cS[1][jj], qf[1][2 * s2],     bc[0], bc[1]);
                    mma16816(cS[0][jj], qf[0][2 * s2 + 1], bc[2], bc[3]);
                    mma16816(cS[1][jj], qf[1][2 * s2 + 1], bc[2], bc[3]);
                }
            }

            // ---- exp2 -> P A-frags + l accumulation ----
            uint32_t pf[2][4];
            #pragma unroll
            for (int b_ = 0; b_ < 2; b_++) {
                pf[b_][0] = ex2_h2(pack_h2(cS[b_][0][0], cS[b_][0][1]));
                pf[b_][1] = ex2_h2(pack_h2(cS[b_][0][2], cS[b_][0][3]));
                pf[b_][2] = ex2_h2(pack_h2(cS[b_][1][0], cS[b_][1][1]));
                pf[b_][3] = ex2_h2(pack_h2(cS[b_][1][2], cS[b_][1][3]));
                __half2 s0 = __hadd2(*(__half2*)&pf[b_][0], *(__half2*)&pf[b_][2]);
                __half2 s1 = __hadd2(*(__half2*)&pf[b_][1], *(__half2*)&pf[b_][3]);
                float2 f0 = __half22float2(s0);
                float2 f1 = __half22float2(s1);
                lacc[b_][0] += f0.x + f0.y;
                lacc[b_][1] += f1.x + f1.y;
            }

            // ---- O += P_chunk @ V_chunk: pipelined over 8 jp ldsm steps ----
            {
                const uint32_t vrow = vb + (s * 16 + ((l >> 3) & 1) * 8 + (l & 7)) * KSTR + ((l >> 4) * 8) * 2;
                uint32_t br[2][4];
                ldsm4t(br[0], vrow);
                #pragma unroll
                for (int jp = 0; jp < 8; jp++) {
                    if (jp < 7) ldsm4t(br[(jp + 1) & 1], vrow + (jp + 1) * 32);
                    const uint32_t* bc = br[jp & 1];
                    mma16816(cO[0][2 * jp],     pf[0], bc[0], bc[1]);
                    mma16816(cO[1][2 * jp],     pf[1], bc[0], bc[1]);
                    mma16816(cO[0][2 * jp + 1], pf[0], bc[2], bc[3]);
                    mma16816(cO[1][2 * jp + 1], pf[1], bc[2], bc[3]);
                }
            }
        }
    }

    // ---- epilogue: unnormalized partials + row sums ----
    #pragma unroll
    for (int b_ = 0; b_ < 2; b_++) {
        float l0 = lacc[b_][0], l1 = lacc[b_][1];
        l0 += __shfl_xor_sync(0xffffffffu, l0, 1);
        l0 += __shfl_xor_sync(0xffffffffu, l0, 2);
        l1 += __shfl_xor_sync(0xffffffffu, l1, 1);
        l1 += __shfl_xor_sync(0xffffffffu, l1, 2);
        size_t row = (size_t)b * LL + qt * 128 + w * 32 + b_ * 16 + (l >> 2);
        if ((l & 3) == 0) {
            g_pl[h][row] = l0;
            g_pl[h][row + 8] = l1;
        }
        float* po = g_po[h] + row * DD + 2 * (l & 3);
        #pragma unroll
        for (int j = 0; j < 16; j++) {
            *(float2*)(po + j * 8)          = make_float2(cO[b_][j][0], cO[b_][j][1]);
            *(float2*)(po + 8 * DD + j * 8) = make_float2(cO[b_][j][2], cO[b_][j][3]);
        }
    }
}

// ---------------------------------------------------------------------------
// combine: out = (O0 + O1) / (l0 + l1)
// ---------------------------------------------------------------------------
__global__ __launch_bounds__(256) void combine_kernel(float* __restrict__ out)
{
    int gid = blockIdx.x * 256 + threadIdx.x;
    int row = gid >> 5;
    float inv = 1.0f / (g_pl[0][row] + g_pl[1][row]);
    float4 a = ((const float4*)g_po[0])[gid];
    float4 c = ((const float4*)g_po[1])[gid];
    ((float4*)out)[gid] = make_float4((a.x + c.x) * inv, (a.y + c.y) * inv,
                                      (a.z + c.z) * inv, (a.w + c.w) * inv);
}

// ---------------------------------------------------------------------------
extern "C" void kernel_launch(void* const* d_in, const int* in_sizes, int n_in,
                              void* d_out, int out_size)
{
    const float* x1 = (const float*)d_in[0];
    const float* x2 = (const float*)d_in[1];
    const float* x3 = (const float*)d_in[2];
    const float* Wq = (const float*)d_in[3];
    const float* bq = (const float*)d_in[4];
    const float* Wk = (const float*)d_in[5];
    const float* bk = (const float*)d_in[6];
    const float* Wv = (const float*)d_in[7];
    const float* bv = (const float*)d_in[8];
    float* out = (float*)d_out;

    cudaFuncSetAttribute(proj_mma, cudaFuncAttributeMaxDynamicSharedMemorySize, PJ2_SMEM);
    cudaFuncSetAttribute(attn_kernel, cudaFuncAttributeMaxDynamicSharedMemorySize, SMEMSZ);

    wconv_kernel<<<24, 256>>>(Wq, bq, Wk, bk, Wv, bv);
    proj_mma<<<3 * 128, 256, PJ2_SMEM>>>(x1, x2, x3);
    attn_kernel<<<BB * 32 * 2, 128, SMEMSZ>>>();
    combine_kernel<<<(BB * LL * DD) / (4 * 256), 256>>>(out);
}

// round 15
// speedup vs baseline: 1.0766x; 1.0766x over previous
#include <cuda_runtime.h>
#include <cuda_fp16.h>
#include <cstdint>

#define BB 4
#define LL 4096
#define DD 128
#define HTILE 32            // KV tiles per CTA (KV-split by 2)
#define KSTR 272            // K/V smem row stride bytes (128 halfs + 16B pad)
#define KBUF (64 * KSTR)    // 17408
#define VOFFS (3 * KBUF)
#define SMEMSZ (6 * KBUF)   // 104448

// projected q (pre-scaled by log2e/sqrt(D)), k, v in fp16
__device__ __half g_qkv[3][(size_t)BB * LL * DD];
// KV-split partials
__device__ float g_po[2][(size_t)BB * LL * DD];
__device__ float g_pl[2][(size_t)BB * LL];

// ---------------------------------------------------------------------------
// helpers
// ---------------------------------------------------------------------------
__device__ __forceinline__ uint32_t smem_u32(const void* p) {
    uint32_t a;
    asm("{ .reg .u64 t; cvta.to.shared.u64 t, %1; cvt.u32.u64 %0, t; }" : "=r"(a) : "l"(p));
    return a;
}
__device__ __forceinline__ void cp_async16(uint32_t dst, const void* src) {
    asm volatile("cp.async.cg.shared.global [%0], [%1], 16;" :: "r"(dst), "l"(src));
}
#define CP_COMMIT() asm volatile("cp.async.commit_group;" ::: "memory")
#define CP_WAIT(n)  asm volatile("cp.async.wait_group %0;" :: "n"(n) : "memory")

__device__ __forceinline__ void ldsm4(uint32_t* r, uint32_t a) {
    asm volatile("ldmatrix.sync.aligned.m8n8.x4.shared.b16 {%0,%1,%2,%3}, [%4];"
                 : "=r"(r[0]), "=r"(r[1]), "=r"(r[2]), "=r"(r[3]) : "r"(a));
}
__device__ __forceinline__ void ldsm4t(uint32_t* r, uint32_t a) {
    asm volatile("ldmatrix.sync.aligned.m8n8.x4.trans.shared.b16 {%0,%1,%2,%3}, [%4];"
                 : "=r"(r[0]), "=r"(r[1]), "=r"(r[2]), "=r"(r[3]) : "r"(a));
}
__device__ __forceinline__ void mma16816(float* c, const uint32_t* a, uint32_t b0, uint32_t b1) {
    asm volatile("mma.sync.aligned.m16n8k16.row.col.f32.f16.f16.f32 "
                 "{%0,%1,%2,%3}, {%4,%5,%6,%7}, {%8,%9}, {%0,%1,%2,%3};"
                 : "+f"(c[0]), "+f"(c[1]), "+f"(c[2]), "+f"(c[3])
                 : "r"(a[0]), "r"(a[1]), "r"(a[2]), "r"(a[3]), "r"(b0), "r"(b1));
}
__device__ __forceinline__ uint32_t ex2_h2(uint32_t x) {
    uint32_t y;
    asm("ex2.approx.f16x2 %0, %1;" : "=r"(y) : "r"(x));
    return y;
}
__device__ __forceinline__ uint32_t pack_h2(float a, float b) {
    __half2 h = __floats2half2_rn(a, b);
    return *(uint32_t*)&h;
}

// ---------------------------------------------------------------------------
// Projection via mma.sync (R8 version — known 17.2us)
// ---------------------------------------------------------------------------
#define PJ_XS 0
#define PJ_WS 34816
#define PJ_BS 69632
#define PJ_SMEM 70144

__global__ __launch_bounds__(256) void proj_mma(
    const float* __restrict__ x1, const float* __restrict__ x2, const float* __restrict__ x3,
    const float* __restrict__ Wq, const float* __restrict__ bq,
    const float* __restrict__ Wk, const float* __restrict__ bk,
    const float* __restrict__ Wv, const float* __restrict__ bv)
{
    extern __shared__ char psm[];
    const uint32_t sb = smem_u32(psm);
    const int tid = threadIdx.x;
    const int w = tid >> 5;
    const int l = tid & 31;
    const int sel = blockIdx.x >> 7;
    const int blk = blockIdx.x & 127;

    const float* x = (sel == 0) ? x1 : (sel == 1) ? x2 : x3;
    const float* W = (sel == 0) ? Wq : (sel == 1) ? Wk : Wv;
    const float* bias = (sel == 0) ? bq : (sel == 1) ? bk : bv;
    const float scale = (sel == 0) ? 0.12752615f : 1.0f;   // log2(e)/sqrt(128)
    __half* out = g_qkv[sel] + (size_t)blk * 128 * DD;

    const float4* xg = (const float4*)(x + (size_t)blk * 128 * DD);
    const float4* wg = (const float4*)W;
    #pragma unroll
    for (int i = 0; i < 16; i++) {
        int idx = tid + i * 256;
        int r = idx >> 5, c = idx & 31;
        float4 v = xg[idx];
        *(uint2*)(psm + PJ_XS + r * KSTR + c * 8) = make_uint2(pack_h2(v.x, v.y), pack_h2(v.z, v.w));
        float4 u = wg[idx];
        *(uint2*)(psm + PJ_WS + r * KSTR + c * 8) = make_uint2(pack_h2(u.x, u.y), pack_h2(u.z, u.w));
    }
    if (tid < 128) ((float*)(psm + PJ_BS))[tid] = bias[tid];
    __syncthreads();

    uint32_t af[8][4];
    const uint32_t abase = sb + PJ_XS + (w * 16 + (l & 7) + ((l >> 3) & 1) * 8) * KSTR + ((l >> 4) * 8) * 2;
    #pragma unroll
    for (int s = 0; s < 8; s++) ldsm4(af[s], abase + s * 32);

    float cY[16][4];
    #pragma unroll
    for (int j = 0; j < 16; j++)
        #pragma unroll
        for (int i = 0; i < 4; i++) cY[j][i] = 0.f;

    #pragma unroll
    for (int j = 0; j < 16; j++) {
        const uint32_t bbase = sb + PJ_WS + (j * 8 + (l & 7)) * KSTR + ((l >> 3) * 8) * 2;
        #pragma unroll
        for (int s2 = 0; s2 < 4; s2++) {
            uint32_t br[4];
            ldsm4(br, bbase + s2 * 64);
            mma16816(cY[j], af[2 * s2],     br[0], br[1]);
            mma16816(cY[j], af[2 * s2 + 1], br[2], br[3]);
        }
    }

    const float* bs = (const float*)(psm + PJ_BS);
    __half* o0 = out + (w * 16 + (l >> 2)) * DD;
    #pragma unroll
    for (int j = 0; j < 16; j++) {
        int c = j * 8 + 2 * (l & 3);
        float b0 = bs[c], b1 = bs[c + 1];
        *(uint32_t*)(o0 + c)          = pack_h2((cY[j][0] + b0) * scale, (cY[j][1] + b1) * scale);
        *(uint32_t*)(o0 + 8 * DD + c) = pack_h2((cY[j][2] + b0) * scale, (cY[j][3] + b1) * scale);
    }
}

// ---------------------------------------------------------------------------
// fp16 mma.sync flash attention, 32 q-rows/warp, chunked streaming softmax,
// register P, KV-split x2. PV(s) fused with S(s+1); chunk loop kept rolled
// (#pragma unroll 1) to bound code size / ptxas effort.
// ---------------------------------------------------------------------------
__device__ __forceinline__ void load_kv(const __half* kg, const __half* vg, int t,
                                        uint32_t sb, int buf, int tid)
{
    const __half* ks = kg + (size_t)t * 64 * DD;
    const __half* vs = vg + (size_t)t * 64 * DD;
    const uint32_t kd = sb + buf * KBUF;
    const uint32_t vd = sb + VOFFS + buf * KBUF;
    #pragma unroll
    for (int i = 0; i < 8; i++) {
        int idx = tid + i * 128;
        int r = idx >> 4, c = idx & 15;
        cp_async16(kd + r * KSTR + c * 16, ks + r * DD + c * 8);
    }
    #pragma unroll
    for (int i = 0; i < 8; i++) {
        int idx = tid + i * 128;
        int r = idx >> 4, c = idx & 15;
        cp_async16(vd + r * KSTR + c * 16, vs + r * DD + c * 8);
    }
}

__global__ __launch_bounds__(128, 2) void attn_kernel()
{
    extern __shared__ char smem[];
    const uint32_t sb = smem_u32(smem);
    const int tid = threadIdx.x;
    const int w = tid >> 5;
    const int l = tid & 31;
    const int b  = blockIdx.x >> 6;
    const int qt = (blockIdx.x >> 1) & 31;
    const int h  = blockIdx.x & 1;

    const __half* qg = g_qkv[0] + ((size_t)b * LL + qt * 128) * DD;
    const __half* kg = g_qkv[1] + ((size_t)b * LL + h * 2048) * DD;
    const __half* vg = g_qkv[2] + ((size_t)b * LL + h * 2048) * DD;

    uint32_t qf[2][8][4];
    #pragma unroll
    for (int b_ = 0; b_ < 2; b_++) {
        const __half* q0 = qg + (w * 32 + b_ * 16 + (l >> 2)) * DD + 2 * (l & 3);
        #pragma unroll
        for (int s = 0; s < 8; s++) {
            qf[b_][s][0] = *(const uint32_t*)(q0 + 16 * s);
            qf[b_][s][1] = *(const uint32_t*)(q0 + 8 * DD + 16 * s);
            qf[b_][s][2] = *(const uint32_t*)(q0 + 16 * s + 8);
            qf[b_][s][3] = *(const uint32_t*)(q0 + 8 * DD + 16 * s + 8);
        }
    }

    load_kv(kg, vg, 0, sb, 0, tid); CP_COMMIT();
    load_kv(kg, vg, 1, sb, 1, tid); CP_COMMIT();

    float cO[2][16][4];
    #pragma unroll
    for (int b_ = 0; b_ < 2; b_++)
        #pragma unroll
        for (int j = 0; j < 16; j++)
            #pragma unroll
            for (int i = 0; i < 4; i++) cO[b_][j][i] = 0.f;
    float lacc[2][2] = {{0.f, 0.f}, {0.f, 0.f}};

    for (int t = 0; t < HTILE; t++) {
        if (t + 2 < HTILE) { CP_WAIT(1); } else { CP_WAIT(0); }
        __syncthreads();
        if (t + 2 < HTILE) { load_kv(kg, vg, t + 2, sb, (t + 2) % 3, tid); CP_COMMIT(); }

        const uint32_t kb = sb + (t % 3) * KBUF;
        const uint32_t vb = sb + VOFFS + (t % 3) * KBUF;

        float cS[2][2][4];
        #pragma unroll
        for (int b_ = 0; b_ < 2; b_++)
            #pragma unroll
            for (int jj = 0; jj < 2; jj++)
                #pragma unroll
                for (int i = 0; i < 4; i++) cS[b_][jj][i] = 0.f;

        // ---- prologue: S(chunk 0) ----
        #pragma unroll
        for (int jj = 0; jj < 2; jj++) {
            const uint32_t krow = kb + (jj * 8 + (l & 7)) * KSTR + ((l >> 3) * 8) * 2;
            #pragma unroll
            for (int s2 = 0; s2 < 4; s2++) {
                uint32_t br[4];
                ldsm4(br, krow + s2 * 64);
                mma16816(cS[0][jj], qf[0][2 * s2],     br[0], br[1]);
                mma16816(cS[1][jj], qf[1][2 * s2],     br[0], br[1]);
                mma16816(cS[0][jj], qf[0][2 * s2 + 1], br[2], br[3]);
                mma16816(cS[1][jj], qf[1][2 * s2 + 1], br[2], br[3]);
            }
        }

        #pragma unroll 1
        for (int s = 0; s < 4; s++) {
            // ---- exp2(S(s)) -> P A-frags + l accumulation ----
            uint32_t pf[2][4];
            #pragma unroll
            for (int b_ = 0; b_ < 2; b_++) {
                pf[b_][0] = ex2_h2(pack_h2(cS[b_][0][0], cS[b_][0][1]));
                pf[b_][1] = ex2_h2(pack_h2(cS[b_][0][2], cS[b_][0][3]));
                pf[b_][2] = ex2_h2(pack_h2(cS[b_][1][0], cS[b_][1][1]));
                pf[b_][3] = ex2_h2(pack_h2(cS[b_][1][2], cS[b_][1][3]));
                __half2 s0 = __hadd2(*(__half2*)&pf[b_][0], *(__half2*)&pf[b_][2]);
                __half2 s1 = __hadd2(*(__half2*)&pf[b_][1], *(__half2*)&pf[b_][3]);
                float2 f0 = __half22float2(s0);
                float2 f1 = __half22float2(s1);
                lacc[b_][0] += f0.x + f0.y;
                lacc[b_][1] += f1.x + f1.y;
            }

            #pragma unroll
            for (int b_ = 0; b_ < 2; b_++)
                #pragma unroll
                for (int jj = 0; jj < 2; jj++)
                    #pragma unroll
                    for (int i = 0; i < 4; i++) cS[b_][jj][i] = 0.f;

            const uint32_t vrow = vb + (s * 16 + ((l >> 3) & 1) * 8 + (l & 7)) * KSTR + ((l >> 4) * 8) * 2;

            if (s < 3) {
                // ---- fused: PV(s) + S(s+1) — two independent MMA chains ----
                const uint32_t kr0 = kb + ((2 * (s + 1) + 0) * 8 + (l & 7)) * KSTR + ((l >> 3) * 8) * 2;
                const uint32_t kr1 = kb + ((2 * (s + 1) + 1) * 8 + (l & 7)) * KSTR + ((l >> 3) * 8) * 2;
                #pragma unroll
                for (int i = 0; i < 8; i++) {
                    const int jj = i >> 2, s2 = i & 3;
                    uint32_t vr[4], kr[4];
                    ldsm4t(vr, vrow + i * 32);
                    ldsm4(kr, (jj ? kr1 : kr0) + s2 * 64);
                    mma16816(cO[0][2 * i],     pf[0], vr[0], vr[1]);
                    mma16816(cS[0][jj], qf[0][2 * s2],     kr[0], kr[1]);
                    mma16816(cO[1][2 * i],     pf[1], vr[0], vr[1]);
                    mma16816(cS[1][jj], qf[1][2 * s2],     kr[0], kr[1]);
                    mma16816(cO[0][2 * i + 1], pf[0], vr[2], vr[3]);
                    mma16816(cS[0][jj], qf[0][2 * s2 + 1], kr[2], kr[3]);
                    mma16816(cO[1][2 * i + 1], pf[1], vr[2], vr[3]);
                    mma16816(cS[1][jj], qf[1][2 * s2 + 1], kr[2], kr[3]);
                }
            } else {
                // ---- last chunk of tile: PV only ----
                #pragma unroll
                for (int jp = 0; jp < 8; jp++) {
                    uint32_t vr[4];
                    ldsm4t(vr, vrow + jp * 32);
                    mma16816(cO[0][2 * jp],     pf[0], vr[0], vr[1]);
                    mma16816(cO[1][2 * jp],     pf[1], vr[0], vr[1]);
                    mma16816(cO[0][2 * jp + 1], pf[0], vr[2], vr[3]);
                    mma16816(cO[1][2 * jp + 1], pf[1], vr[2], vr[3]);
                }
            }
        }
    }

    // ---- epilogue: unnormalized partials + row sums ----
    #pragma unroll
    for (int b_ = 0; b_ < 2; b_++) {
        float l0 = lacc[b_][0], l1 = lacc[b_][1];
        l0 += __shfl_xor_sync(0xffffffffu, l0, 1);
        l0 += __shfl_xor_sync(0xffffffffu, l0, 2);
        l1 += __shfl_xor_sync(0xffffffffu, l1, 1);
        l1 += __shfl_xor_sync(0xffffffffu, l1, 2);
        size_t row = (size_t)b * LL + qt * 128 + w * 32 + b_ * 16 + (l >> 2);
        if ((l & 3) == 0) {
            g_pl[h][row] = l0;
            g_pl[h][row + 8] = l1;
        }
        float* po = g_po[h] + row * DD + 2 * (l & 3);
        #pragma unroll
        for (int j = 0; j < 16; j++) {
            *(float2*)(po + j * 8)          = make_float2(cO[b_][j][0], cO[b_][j][1]);
            *(float2*)(po + 8 * DD + j * 8) = make_float2(cO[b_][j][2], cO[b_][j][3]);
        }
    }
}

// ---------------------------------------------------------------------------
// combine: out = (O0 + O1) / (l0 + l1)
// ---------------------------------------------------------------------------
__global__ __launch_bounds__(256) void combine_kernel(float* __restrict__ out)
{
    int gid = blockIdx.x * 256 + threadIdx.x;
    int row = gid >> 5;
    float inv = 1.0f / (g_pl[0][row] + g_pl[1][row]);
    float4 a = ((const float4*)g_po[0])[gid];
    float4 c = ((const float4*)g_po[1])[gid];
    ((float4*)out)[gid] = make_float4((a.x + c.x) * inv, (a.y + c.y) * inv,
                                      (a.z + c.z) * inv, (a.w + c.w) * inv);
}

// ---------------------------------------------------------------------------
extern "C" void kernel_launch(void* const* d_in, const int* in_sizes, int n_in,
                              void* d_out, int out_size)
{
    const float* x1 = (const float*)d_in[0];
    const float* x2 = (const float*)d_in[1];
    const float* x3 = (const float*)d_in[2];
    const float* Wq = (const float*)d_in[3];
    const float* bq = (const float*)d_in[4];
    const float* Wk = (const float*)d_in[5];
    const float* bk = (const float*)d_in[6];
    const float* Wv = (const float*)d_in[7];
    const float* bv = (const float*)d_in[8];
    float* out = (float*)d_out;

    cudaFuncSetAttribute(proj_mma, cudaFuncAttributeMaxDynamicSharedMemorySize, PJ_SMEM);
    cudaFuncSetAttribute(attn_kernel, cudaFuncAttributeMaxDynamicSharedMemorySize, SMEMSZ);

    proj_mma<<<3 * 128, 256, PJ_SMEM>>>(x1, x2, x3, Wq, bq, Wk, bk, Wv, bv);
    attn_kernel<<<BB * 32 * 2, 128, SMEMSZ>>>();
    combine_kernel<<<(BB * LL * DD) / (4 * 256), 256>>>(out);
}